// round 15
// baseline (speedup 1.0000x reference)
#include <cuda_runtime.h>
#include <cstdint>
#include <math.h>

#define Dd 768
#define Hh 768
#define Ee 128
#define Bb 32
#define Ss 128
#define LN_EPS 1e-5f

// Scratch (static device arrays are allowed)
__device__ float g_q[Ee * Ss * Hh];    // pre-rounded tf32 (bit patterns)
__device__ float g_k[Bb * Ss * Hh];    // pre-rounded tf32
__device__ float g_v[Bb * Ss * Hh];    // exact fp32
__device__ float g_c[Ee * Hh];         // exact fp32
__device__ float g_pbar[Ee * Bb * Ss]; // column sums of softmax probs
// tf32-rounded copies of inputs
__device__ float g_etok[Ee * Ss * Dd];
__device__ float g_mtok[Bb * Ss * Dd];
__device__ float g_ecls[Ee * Dd];
// tf32-rounded TRANSPOSED weights: [n][k]
__device__ float g_wq[Hh * Dd];
__device__ float g_wk[Hh * Dd];
__device__ float g_wv[Hh * Dd];
__device__ float g_wc[Hh * Dd];

// ---------------------------------------------------------------------------
// helpers
// ---------------------------------------------------------------------------
__device__ __forceinline__ uint32_t f2tf(float x) {
    uint32_t r;
    asm("cvt.rna.tf32.f32 %0, %1;" : "=r"(r) : "f"(x));
    return r;
}

__device__ __forceinline__ uint32_t smem_u32(const void* p) {
    uint32_t a;
    asm("{ .reg .u64 t; cvta.to.shared.u64 t, %1; cvt.u32.u64 %0, t; }"
        : "=r"(a) : "l"(p));
    return a;
}

// L1-bypass async copy (no intra-CTA reuse of these bytes)
__device__ __forceinline__ void cp16(uint32_t dst, const void* src) {
    asm volatile("cp.async.cg.shared.global [%0], [%1], 16;"
                 :: "r"(dst), "l"(src));
}
#define CP_COMMIT() asm volatile("cp.async.commit_group;" ::: "memory")
#define CP_WAIT0()  asm volatile("cp.async.wait_group 0;" ::: "memory")

__device__ __forceinline__ void mma_tf32(float* c, const uint32_t* a,
                                         uint32_t b0, uint32_t b1) {
    asm volatile(
        "mma.sync.aligned.m16n8k8.row.col.f32.tf32.tf32.f32 "
        "{%0,%1,%2,%3}, {%4,%5,%6,%7}, {%8,%9}, {%0,%1,%2,%3};\n"
        : "+f"(c[0]), "+f"(c[1]), "+f"(c[2]), "+f"(c[3])
        : "r"(a[0]), "r"(a[1]), "r"(a[2]), "r"(a[3]), "r"(b0), "r"(b1));
}

__device__ __forceinline__ void ldsm4(uint32_t& r0, uint32_t& r1,
                                      uint32_t& r2, uint32_t& r3, uint32_t addr) {
    asm volatile("ldmatrix.sync.aligned.m8n8.x4.shared.b16 {%0,%1,%2,%3}, [%4];"
                 : "=r"(r0), "=r"(r1), "=r"(r2), "=r"(r3) : "r"(addr));
}

// ---------------------------------------------------------------------------
// Merged prep pass: activation rounding + weight transpose/round, one launch.
// blocks [0, NB_ROUND): float4 rounding of etok/mtok/ecls
// blocks [NB_ROUND, NB_ROUND+2304): 32x32 transpose tiles of Wq/Wk/Wv/Wc
// ---------------------------------------------------------------------------
#define N4_ETOK (Ee * Ss * Dd / 4)
#define N4_MTOK (Bb * Ss * Dd / 4)
#define N4_ECLS (Ee * Dd / 4)
#define N4_TOTAL (N4_ETOK + N4_MTOK + N4_ECLS)
#define NB_ROUND (N4_TOTAL / 256)            // 15456 (exact)
#define NB_WT    (24 * 24 * 4)               // 2304
#define NB_PREP  (NB_ROUND + NB_WT)

__global__ __launch_bounds__(256)
void prep(const float* __restrict__ etok, const float* __restrict__ mtok,
          const float* __restrict__ ecls,
          const float* __restrict__ Wq, const float* __restrict__ Wk,
          const float* __restrict__ Wv, const float* __restrict__ Wc)
{
    __shared__ float t[32][33];
    const int bid = blockIdx.x;
    const int tid = threadIdx.x;

    if (bid < NB_ROUND) {
        int idx = bid * 256 + tid;
        const float4* src;
        float4* dst;
        int off = idx;
        if (off < N4_ETOK) { src = (const float4*)etok; dst = (float4*)g_etok; }
        else if ((off -= N4_ETOK) < N4_MTOK) { src = (const float4*)mtok; dst = (float4*)g_mtok; }
        else { off -= N4_MTOK; src = (const float4*)ecls; dst = (float4*)g_ecls; }
        float4 v = src[off];
        float4 o;
        o.x = __uint_as_float(f2tf(v.x));
        o.y = __uint_as_float(f2tf(v.y));
        o.z = __uint_as_float(f2tf(v.z));
        o.w = __uint_as_float(f2tf(v.w));
        dst[off] = o;
        return;
    }

    // transpose segment
    int w = bid - NB_ROUND;
    int z = w / 576;
    int rem = w - z * 576;
    int bx = rem % 24, by = rem / 24;
    const float* W;
    float* Wt;
    switch (z) {
        case 0: W = Wq; Wt = g_wq; break;
        case 1: W = Wk; Wt = g_wk; break;
        case 2: W = Wv; Wt = g_wv; break;
        default: W = Wc; Wt = g_wc; break;
    }
    const int tx = tid & 31, ty = tid >> 5;
    const int x = bx * 32 + tx;      // n
    const int y0 = by * 32;          // k base
#pragma unroll
    for (int j = 0; j < 32; j += 8)
        t[ty + j][tx] = W[(size_t)(y0 + ty + j) * Hh + x];
    __syncthreads();
    const int xn = bx * 32;
#pragma unroll
    for (int j = 0; j < 32; j += 8)
        Wt[(size_t)(xn + ty + j) * Dd + y0 + tx] =
            __uint_as_float(f2tf(t[tx][ty + j]));
}

// ---------------------------------------------------------------------------
// Merged projection: attn-style mainloop, BOTH operands via ldmatrix.
// ---------------------------------------------------------------------------
#define TILE_BYTES (128 * 36 * 4)          // 18432
#define STAGE_BYTES (2 * TILE_BYTES)       // 36864
#define OFF_TILE 1024
#define GEMM_SMEM (OFF_TILE + 2 * STAGE_BYTES)

__global__ __launch_bounds__(128, 3)
void proj_mma(const float* __restrict__ bq, const float* __restrict__ bk,
              const float* __restrict__ bv, const float* __restrict__ bc,
              float* __restrict__ Yq, float* __restrict__ Yk,
              float* __restrict__ Yv, float* __restrict__ Yc)
{
    extern __shared__ char smem[];

    const int tid = threadIdx.x;
    const int wid = tid >> 5;
    const int lane = tid & 31;
    const int gid = lane >> 2;
    const int tg = lane & 3;
    const int wm = wid & 1;
    const int wn = wid >> 1;
    const int n0 = blockIdx.x << 7;

    const int by = blockIdx.y;
    const float *X, *Wt, *bias;
    float* Y;
    int m0, rnd;
    if (by < 128)      { X = g_etok; Wt = g_wq; bias = bq; Y = Yq; m0 = by << 7;         rnd = 1; }
    else if (by < 160) { X = g_mtok; Wt = g_wk; bias = bk; Y = Yk; m0 = (by - 128) << 7; rnd = 1; }
    else if (by < 192) { X = g_mtok; Wt = g_wv; bias = bv; Y = Yv; m0 = (by - 160) << 7; rnd = 0; }
    else               { X = g_ecls; Wt = g_wc; bias = bc; Y = Yc; m0 = 0;               rnd = 0; }

    const uint32_t stile = smem_u32(smem) + OFF_TILE;

    const int lq = lane >> 3, lr = lane & 7;
    const int rowA = (wm * 64 + (lq & 1) * 8 + lr) * 36 + (lq >> 1) * 4;
    const int rowB = (wn * 64 + (lq >> 1) * 8 + lr) * 36 + (lq & 1) * 4;

    float c[4][8][4];
#pragma unroll
    for (int mt = 0; mt < 4; mt++)
#pragma unroll
        for (int nt = 0; nt < 8; nt++)
#pragma unroll
            for (int q = 0; q < 4; q++) c[mt][nt][q] = 0.0f;

    auto issue = [&](int kt, int s) {
        uint32_t ab = stile + s * STAGE_BYTES;
        uint32_t bb = ab + TILE_BYTES;
#pragma unroll
        for (int it = 0; it < 8; ++it) {
            int idx = tid + (it << 7);
            int r = idx >> 3, c4 = (idx & 7) << 2;
            uint32_t off = (uint32_t)(r * 36 + c4) * 4;
            cp16(ab + off, &X[(size_t)(m0 + r) * Dd + kt * 32 + c4]);
            cp16(bb + off, &Wt[(size_t)(n0 + r) * Dd + kt * 32 + c4]);
        }
    };

    issue(0, 0);
    CP_COMMIT();

    const int NKT = Dd / 32;  // 24
    for (int kt = 0; kt < NKT; ++kt) {
        CP_WAIT0();
        __syncthreads();
        if (kt + 1 < NKT) {
            issue(kt + 1, (kt + 1) & 1);
            CP_COMMIT();
        }

        const uint32_t ab = stile + (kt & 1) * STAGE_BYTES;
        const uint32_t bb = ab + TILE_BYTES;

#pragma unroll
        for (int ks = 0; ks < 4; ++ks) {
            int k0 = ks << 3;
            uint32_t a[4][4];
#pragma unroll
            for (int mt = 0; mt < 4; mt++)
                ldsm4(a[mt][0], a[mt][1], a[mt][2], a[mt][3],
                      ab + (uint32_t)(rowA + mt * 576 + k0) * 4);
#pragma unroll
            for (int p = 0; p < 4; p++) {
                uint32_t b0a, b1a, b0b, b1b;
                ldsm4(b0a, b1a, b0b, b1b,
                      bb + (uint32_t)(rowB + p * 576 + k0) * 4);
#pragma unroll
                for (int mt = 0; mt < 4; mt++)
                    mma_tf32(c[mt][2 * p], a[mt], b0a, b1a);
#pragma unroll
                for (int mt = 0; mt < 4; mt++)
                    mma_tf32(c[mt][2 * p + 1], a[mt], b0b, b1b);
            }
        }
    }

#pragma unroll
    for (int nt = 0; nt < 8; nt++) {
        int col = n0 + wn * 64 + nt * 8 + 2 * tg;
        float2 bvv = *(const float2*)&bias[col];
#pragma unroll
        for (int mt = 0; mt < 4; mt++) {
            int r = m0 + wm * 64 + mt * 16 + gid;
            float2 o0 = {c[mt][nt][0] + bvv.x, c[mt][nt][1] + bvv.y};
            float2 o1 = {c[mt][nt][2] + bvv.x, c[mt][nt][3] + bvv.y};
            if (rnd) {
                o0.x = __uint_as_float(f2tf(o0.x));
                o0.y = __uint_as_float(f2tf(o0.y));
                o1.x = __uint_as_float(f2tf(o1.x));
                o1.y = __uint_as_float(f2tf(o1.y));
            }
            *(float2*)&Y[(size_t)r * Hh + col] = o0;
            *(float2*)&Y[(size_t)(r + 8) * Hh + col] = o1;
        }
    }
}

// ---------------------------------------------------------------------------
// Attention core: one CTA per (e,b), 128 threads (4 warps, 64x64 tiles).
//   Fragment-register softmax + pbar (no P smem round trip).
// ---------------------------------------------------------------------------
#define ATTN_SMEM (OFF_TILE + 2 * STAGE_BYTES)

__global__ __launch_bounds__(128, 3)
void attn_mma(float* __restrict__ pbar_out)
{
    extern __shared__ char smem[];

    const int tid = threadIdx.x;
    const int wid = tid >> 5;
    const int lane = tid & 31;
    const int gid = lane >> 2;
    const int tg = lane & 3;
    const int wm = wid & 1;
    const int wn = wid >> 1;
    const int e = blockIdx.x >> 5;
    const int b = blockIdx.x & 31;

    const float* __restrict__ Q = g_q + (size_t)e * Ss * Hh;
    const float* __restrict__ K = g_k + (size_t)b * Ss * Hh;

    const uint32_t stile = smem_u32(smem) + OFF_TILE;

    const int lq = lane >> 3, lr = lane & 7;
    const int rowA = (wm * 64 + (lq & 1) * 8 + lr) * 36 + (lq >> 1) * 4;
    const int rowB = (wn * 64 + (lq >> 1) * 8 + lr) * 36 + (lq & 1) * 4;

    float c[4][8][4];
#pragma unroll
    for (int mt = 0; mt < 4; mt++)
#pragma unroll
        for (int nt = 0; nt < 8; nt++)
#pragma unroll
            for (int q = 0; q < 4; q++) c[mt][nt][q] = 0.0f;

    auto issue = [&](int kt, int s) {
        uint32_t qb = stile + s * STAGE_BYTES;
        uint32_t kb = qb + TILE_BYTES;
#pragma unroll
        for (int it = 0; it < 8; ++it) {
            int idx = tid + (it << 7);
            int r = idx >> 3, c4 = (idx & 7) << 2;
            uint32_t off = (uint32_t)(r * 36 + c4) * 4;
            cp16(qb + off, &Q[(size_t)r * Hh + kt * 32 + c4]);
            cp16(kb + off, &K[(size_t)r * Hh + kt * 32 + c4]);
        }
    };

    issue(0, 0);
    CP_COMMIT();

    const int NKT = Hh / 32;  // 24
    for (int kt = 0; kt < NKT; ++kt) {
        CP_WAIT0();
        __syncthreads();
        if (kt + 1 < NKT) {
            issue(kt + 1, (kt + 1) & 1);
            CP_COMMIT();
        }

        const uint32_t qb = stile + (kt & 1) * STAGE_BYTES;
        const uint32_t kb = qb + TILE_BYTES;

#pragma unroll
        for (int ks = 0; ks < 4; ++ks) {
            int k0 = ks << 3;
            uint32_t a[4][4];
#pragma unroll
            for (int mt = 0; mt < 4; mt++)
                ldsm4(a[mt][0], a[mt][1], a[mt][2], a[mt][3],
                      qb + (uint32_t)(rowA + mt * 576 + k0) * 4);
#pragma unroll
            for (int p = 0; p < 4; p++) {
                uint32_t b0a, b1a, b0b, b1b;
                ldsm4(b0a, b1a, b0b, b1b,
                      kb + (uint32_t)(rowB + p * 576 + k0) * 4);
#pragma unroll
                for (int mt = 0; mt < 4; mt++)
                    mma_tf32(c[mt][2 * p], a[mt], b0a, b1a);
#pragma unroll
                for (int mt = 0; mt < 4; mt++)
                    mma_tf32(c[mt][2 * p + 1], a[mt], b0b, b1b);
            }
        }
    }

    // --- register softmax + pbar ---
    float* rowmax = (float*)(smem + OFF_TILE);          // [2][128]
    float* rowsum = (float*)(smem + OFF_TILE + 1024);   // [2][128]
    float* colred = (float*)(smem + OFF_TILE + 2048);   // [2][128]

    const float scale = 0.0360843918243516f;  // 1/sqrt(768)

    float rm[8];
#pragma unroll
    for (int mt = 0; mt < 4; mt++)
#pragma unroll
        for (int hi = 0; hi < 2; hi++) {
            float m = -1e30f;
#pragma unroll
            for (int nt = 0; nt < 8; nt++) {
                m = fmaxf(m, c[mt][nt][hi * 2 + 0]);
                m = fmaxf(m, c[mt][nt][hi * 2 + 1]);
            }
            rm[mt * 2 + hi] = m;
        }
#pragma unroll
    for (int i = 0; i < 8; i++) {
        rm[i] = fmaxf(rm[i], __shfl_xor_sync(0xffffffffu, rm[i], 1));
        rm[i] = fmaxf(rm[i], __shfl_xor_sync(0xffffffffu, rm[i], 2));
    }
    if (tg == 0) {
#pragma unroll
        for (int i = 0; i < 8; i++) {
            int r = wm * 64 + (i >> 1) * 16 + (i & 1) * 8 + gid;
            rowmax[wn * 128 + r] = rm[i];
        }
    }
    __syncthreads();
#pragma unroll
    for (int i = 0; i < 8; i++) {
        int r = wm * 64 + (i >> 1) * 16 + (i & 1) * 8 + gid;
        rm[i] = fmaxf(rm[i], rowmax[(wn ^ 1) * 128 + r]);
    }

    float rs[8];
#pragma unroll
    for (int i = 0; i < 8; i++) rs[i] = 0.0f;
#pragma unroll
    for (int mt = 0; mt < 4; mt++)
#pragma unroll
        for (int nt = 0; nt < 8; nt++)
#pragma unroll
            for (int q = 0; q < 4; q++) {
                int i = mt * 2 + (q >> 1);
                float ev = __expf((c[mt][nt][q] - rm[i]) * scale);
                c[mt][nt][q] = ev;
                rs[i] += ev;
            }
#pragma unroll
    for (int i = 0; i < 8; i++) {
        rs[i] += __shfl_xor_sync(0xffffffffu, rs[i], 1);
        rs[i] += __shfl_xor_sync(0xffffffffu, rs[i], 2);
    }
    if (tg == 0) {
#pragma unroll
        for (int i = 0; i < 8; i++) {
            int r = wm * 64 + (i >> 1) * 16 + (i & 1) * 8 + gid;
            rowsum[wn * 128 + r] = rs[i];
        }
    }
    __syncthreads();
    float inv[8];
#pragma unroll
    for (int i = 0; i < 8; i++) {
        int r = wm * 64 + (i >> 1) * 16 + (i & 1) * 8 + gid;
        inv[i] = 1.0f / (rs[i] + rowsum[(wn ^ 1) * 128 + r]);
    }

    float pp[16];
#pragma unroll
    for (int j = 0; j < 16; j++) pp[j] = 0.0f;
#pragma unroll
    for (int mt = 0; mt < 4; mt++)
#pragma unroll
        for (int nt = 0; nt < 8; nt++)
#pragma unroll
            for (int q = 0; q < 4; q++) {
                int i = mt * 2 + (q >> 1);
                pp[nt * 2 + (q & 1)] += c[mt][nt][q] * inv[i];
            }
#pragma unroll
    for (int j = 0; j < 16; j++) {
        pp[j] += __shfl_xor_sync(0xffffffffu, pp[j], 4);
        pp[j] += __shfl_xor_sync(0xffffffffu, pp[j], 8);
        pp[j] += __shfl_xor_sync(0xffffffffu, pp[j], 16);
    }
    if (gid == 0) {
#pragma unroll
        for (int nt = 0; nt < 8; nt++)
#pragma unroll
            for (int par = 0; par < 2; par++) {
                int col = wn * 64 + nt * 8 + 2 * tg + par;
                colred[wm * 128 + col] = pp[nt * 2 + par];
            }
    }
    __syncthreads();
    if (tid < 128)
        pbar_out[(size_t)blockIdx.x * Ss + tid] = colred[tid] + colred[128 + tid];
}

// ---------------------------------------------------------------------------
// ctx + LN + dual score: grid (16 etiles, 32 b), 256 threads, 8 e per CTA.
// ctx phase: threads 0..191 each own a float4 h-slice (1 LDG.128 per t).
// ---------------------------------------------------------------------------
#define CTX_E 8
#define CTX_STRIDE 776
#define CTX_SMEM (CTX_E * 128 * 4 + CTX_E * CTX_STRIDE * 4)

__global__ __launch_bounds__(256)
void ctx_score(const float* __restrict__ ecls, const float* __restrict__ mcls,
               const float* __restrict__ lng, const float* __restrict__ lnb,
               float* __restrict__ out)
{
    extern __shared__ char smem[];
    float* pb = (float*)smem;                           // [8][128]
    float* ctx_s = (float*)(smem + CTX_E * 128 * 4);    // [8][776]

    const int tid = threadIdx.x;
    const int e0 = blockIdx.x * CTX_E;
    const int b = blockIdx.y;

    const float* __restrict__ V = g_v + (size_t)b * Ss * Hh;

#pragma unroll
    for (int it = 0; it < 4; ++it) {
        int i = tid + it * 256;
        int el = i >> 7, t = i & 127;
        pb[el * 128 + t] = g_pbar[(size_t)((e0 + el) * Bb + b) * Ss + t];
    }
    __syncthreads();

    if (tid < 192) {
        const int h0 = tid * 4;
        float4 acc[CTX_E];
#pragma unroll
        for (int el = 0; el < CTX_E; el++) acc[el] = make_float4(0, 0, 0, 0);

#pragma unroll 4
        for (int t = 0; t < Ss; t++) {
            float4 v = *(const float4*)&V[(size_t)t * Hh + h0];
#pragma unroll
            for (int el = 0; el < CTX_E; el++) {
                float p = pb[el * 128 + t];
                acc[el].x += p * v.x;
                acc[el].y += p * v.y;
                acc[el].z += p * v.z;
                acc[el].w += p * v.w;
            }
        }
        const float invS = 1.0f / (float)Ss;
#pragma unroll
        for (int el = 0; el < CTX_E; el++) {
            float4 o = {acc[el].x * invS, acc[el].y * invS,
                        acc[el].z * invS, acc[el].w * invS};
            *(float4*)&ctx_s[el * CTX_STRIDE + h0] = o;
        }
    }
    __syncthreads();

    const int g = tid >> 5;
    const int i = tid & 31;
    const int eg = e0 + g;
    const float* crow = &ctx_s[g * CTX_STRIDE];

    float lsum = 0.0f, lsq = 0.0f;
#pragma unroll
    for (int j = 0; j < 24; ++j) {
        float x = crow[i + 32 * j];
        lsum += x;
        lsq += x * x;
    }
#pragma unroll
    for (int o = 16; o > 0; o >>= 1) {
        lsum += __shfl_xor_sync(0xffffffffu, lsum, o);
        lsq  += __shfl_xor_sync(0xffffffffu, lsq, o);
    }
    const float mu = lsum * (1.0f / (float)Hh);
    const float var = lsq * (1.0f / (float)Hh) - mu * mu;
    const float rstd = rsqrtf(var + LN_EPS);

    const float* __restrict__ cfc = g_c + (size_t)eg * Hh;
    const float* __restrict__ er = ecls + (size_t)eg * Dd;
    const float* __restrict__ mr = mcls + (size_t)b * Dd;
    float p1 = 0.0f, p2 = 0.0f;
#pragma unroll
    for (int j = 0; j < 24; ++j) {
        int h = i + 32 * j;
        float x = (crow[h] - mu) * rstd * lng[h] + lnb[h];
        p1 += cfc[h] * x;
        p2 += mr[h] * er[h];
    }
#pragma unroll
    for (int o = 16; o > 0; o >>= 1) {
        p1 += __shfl_xor_sync(0xffffffffu, p1, o);
        p2 += __shfl_xor_sync(0xffffffffu, p2, o);
    }
    if (i == 0) out[(size_t)b * Ee + eg] = 0.5f * (p1 + p2);
}

// ---------------------------------------------------------------------------
extern "C" void kernel_launch(void* const* d_in, const int* in_sizes, int n_in,
                              void* d_out, int out_size)
{
    const float* ecls = (const float*)d_in[0];
    const float* etok = (const float*)d_in[1];
    const float* mcls = (const float*)d_in[2];
    const float* mtok = (const float*)d_in[3];
    const float* Wq = (const float*)d_in[4];
    const float* bq = (const float*)d_in[5];
    const float* Wk = (const float*)d_in[6];
    const float* bk = (const float*)d_in[7];
    const float* Wv = (const float*)d_in[8];
    const float* bv = (const float*)d_in[9];
    const float* Wc = (const float*)d_in[10];
    const float* bc = (const float*)d_in[11];
    const float* lng = (const float*)d_in[12];
    const float* lnb = (const float*)d_in[13];
    float* out = (float*)d_out;

    float *q_ptr, *k_ptr, *v_ptr, *c_ptr, *pbar_ptr;
    cudaGetSymbolAddress((void**)&q_ptr, g_q);
    cudaGetSymbolAddress((void**)&k_ptr, g_k);
    cudaGetSymbolAddress((void**)&v_ptr, g_v);
    cudaGetSymbolAddress((void**)&c_ptr, g_c);
    cudaGetSymbolAddress((void**)&pbar_ptr, g_pbar);

    cudaFuncSetAttribute(proj_mma, cudaFuncAttributeMaxDynamicSharedMemorySize, GEMM_SMEM);
    cudaFuncSetAttribute(attn_mma, cudaFuncAttributeMaxDynamicSharedMemorySize, ATTN_SMEM);
    cudaFuncSetAttribute(ctx_score, cudaFuncAttributeMaxDynamicSharedMemorySize, CTX_SMEM);

    prep<<<NB_PREP, 256>>>(etok, mtok, ecls, Wq, Wk, Wv, Wc);

    proj_mma<<<dim3(Hh / 128, 193), 128, GEMM_SMEM>>>(
        bq, bk, bv, bc, q_ptr, k_ptr, v_ptr, c_ptr);

    attn_mma<<<dim3(Ee * Bb), 128, ATTN_SMEM>>>(pbar_ptr);

    ctx_score<<<dim3(Ee / CTX_E, Bb), 256, CTX_SMEM>>>(ecls, mcls, lng, lnb, out);
}

// round 16
// speedup vs baseline: 1.0382x; 1.0382x over previous
#include <cuda_runtime.h>
#include <cstdint>
#include <math.h>

#define Dd 768
#define Hh 768
#define Ee 128
#define Bb 32
#define Ss 128
#define LN_EPS 1e-5f

// Scratch (static device arrays are allowed)
__device__ float g_q[Ee * Ss * Hh];    // pre-rounded tf32 (bit patterns)
__device__ float g_k[Bb * Ss * Hh];    // pre-rounded tf32
__device__ float g_v[Bb * Ss * Hh];    // exact fp32
__device__ float g_c[Ee * Hh];         // exact fp32
__device__ float g_pbar[Ee * Bb * Ss]; // column sums of softmax probs
// tf32-rounded copies of inputs
__device__ float g_etok[Ee * Ss * Dd];
__device__ float g_mtok[Bb * Ss * Dd];
__device__ float g_ecls[Ee * Dd];
// tf32-rounded TRANSPOSED weights: [n][k]
__device__ float g_wq[Hh * Dd];
__device__ float g_wk[Hh * Dd];
__device__ float g_wv[Hh * Dd];
__device__ float g_wc[Hh * Dd];

// ---------------------------------------------------------------------------
// helpers
// ---------------------------------------------------------------------------
__device__ __forceinline__ uint32_t f2tf(float x) {
    uint32_t r;
    asm("cvt.rna.tf32.f32 %0, %1;" : "=r"(r) : "f"(x));
    return r;
}

__device__ __forceinline__ uint32_t smem_u32(const void* p) {
    uint32_t a;
    asm("{ .reg .u64 t; cvta.to.shared.u64 t, %1; cvt.u32.u64 %0, t; }"
        : "=r"(a) : "l"(p));
    return a;
}

// L1-bypass async copy (no intra-CTA reuse of these bytes)
__device__ __forceinline__ void cp16(uint32_t dst, const void* src) {
    asm volatile("cp.async.cg.shared.global [%0], [%1], 16;"
                 :: "r"(dst), "l"(src));
}
#define CP_COMMIT() asm volatile("cp.async.commit_group;" ::: "memory")
#define CP_WAIT0()  asm volatile("cp.async.wait_group 0;" ::: "memory")

__device__ __forceinline__ void mma_tf32(float* c, const uint32_t* a,
                                         uint32_t b0, uint32_t b1) {
    asm volatile(
        "mma.sync.aligned.m16n8k8.row.col.f32.tf32.tf32.f32 "
        "{%0,%1,%2,%3}, {%4,%5,%6,%7}, {%8,%9}, {%0,%1,%2,%3};\n"
        : "+f"(c[0]), "+f"(c[1]), "+f"(c[2]), "+f"(c[3])
        : "r"(a[0]), "r"(a[1]), "r"(a[2]), "r"(a[3]), "r"(b0), "r"(b1));
}

__device__ __forceinline__ void ldsm4(uint32_t& r0, uint32_t& r1,
                                      uint32_t& r2, uint32_t& r3, uint32_t addr) {
    asm volatile("ldmatrix.sync.aligned.m8n8.x4.shared.b16 {%0,%1,%2,%3}, [%4];"
                 : "=r"(r0), "=r"(r1), "=r"(r2), "=r"(r3) : "r"(addr));
}

// ---------------------------------------------------------------------------
// Merged prep pass: activation rounding + weight transpose/round, one launch.
// ---------------------------------------------------------------------------
#define N4_ETOK (Ee * Ss * Dd / 4)
#define N4_MTOK (Bb * Ss * Dd / 4)
#define N4_ECLS (Ee * Dd / 4)
#define N4_TOTAL (N4_ETOK + N4_MTOK + N4_ECLS)
#define NB_ROUND (N4_TOTAL / 256)
#define NB_WT    (24 * 24 * 4)
#define NB_PREP  (NB_ROUND + NB_WT)

__global__ __launch_bounds__(256)
void prep(const float* __restrict__ etok, const float* __restrict__ mtok,
          const float* __restrict__ ecls,
          const float* __restrict__ Wq, const float* __restrict__ Wk,
          const float* __restrict__ Wv, const float* __restrict__ Wc)
{
    __shared__ float t[32][33];
    const int bid = blockIdx.x;
    const int tid = threadIdx.x;

    if (bid < NB_ROUND) {
        int idx = bid * 256 + tid;
        const float4* src;
        float4* dst;
        int off = idx;
        if (off < N4_ETOK) { src = (const float4*)etok; dst = (float4*)g_etok; }
        else if ((off -= N4_ETOK) < N4_MTOK) { src = (const float4*)mtok; dst = (float4*)g_mtok; }
        else { off -= N4_MTOK; src = (const float4*)ecls; dst = (float4*)g_ecls; }
        float4 v = src[off];
        float4 o;
        o.x = __uint_as_float(f2tf(v.x));
        o.y = __uint_as_float(f2tf(v.y));
        o.z = __uint_as_float(f2tf(v.z));
        o.w = __uint_as_float(f2tf(v.w));
        dst[off] = o;
        return;
    }

    // transpose segment
    int w = bid - NB_ROUND;
    int z = w / 576;
    int rem = w - z * 576;
    int bx = rem % 24, by = rem / 24;
    const float* W;
    float* Wt;
    switch (z) {
        case 0: W = Wq; Wt = g_wq; break;
        case 1: W = Wk; Wt = g_wk; break;
        case 2: W = Wv; Wt = g_wv; break;
        default: W = Wc; Wt = g_wc; break;
    }
    const int tx = tid & 31, ty = tid >> 5;
    const int x = bx * 32 + tx;      // n
    const int y0 = by * 32;          // k base
#pragma unroll
    for (int j = 0; j < 32; j += 8)
        t[ty + j][tx] = W[(size_t)(y0 + ty + j) * Hh + x];
    __syncthreads();
    const int xn = bx * 32;
#pragma unroll
    for (int j = 0; j < 32; j += 8)
        Wt[(size_t)(xn + ty + j) * Dd + y0 + tx] =
            __uint_as_float(f2tf(t[tx][ty + j]));
}

// ---------------------------------------------------------------------------
// Merged projection: attn-style mainloop, BOTH operands via ldmatrix.
// ---------------------------------------------------------------------------
#define TILE_BYTES (128 * 36 * 4)          // 18432
#define STAGE_BYTES (2 * TILE_BYTES)       // 36864
#define OFF_TILE 1024
#define GEMM_SMEM (OFF_TILE + 2 * STAGE_BYTES)

__global__ __launch_bounds__(128, 3)
void proj_mma(const float* __restrict__ bq, const float* __restrict__ bk,
              const float* __restrict__ bv, const float* __restrict__ bc,
              float* __restrict__ Yq, float* __restrict__ Yk,
              float* __restrict__ Yv, float* __restrict__ Yc)
{
    extern __shared__ char smem[];

    const int tid = threadIdx.x;
    const int wid = tid >> 5;
    const int lane = tid & 31;
    const int gid = lane >> 2;
    const int tg = lane & 3;
    const int wm = wid & 1;
    const int wn = wid >> 1;
    const int n0 = blockIdx.x << 7;

    const int by = blockIdx.y;
    const float *X, *Wt, *bias;
    float* Y;
    int m0, rnd;
    if (by < 128)      { X = g_etok; Wt = g_wq; bias = bq; Y = Yq; m0 = by << 7;         rnd = 1; }
    else if (by < 160) { X = g_mtok; Wt = g_wk; bias = bk; Y = Yk; m0 = (by - 128) << 7; rnd = 1; }
    else if (by < 192) { X = g_mtok; Wt = g_wv; bias = bv; Y = Yv; m0 = (by - 160) << 7; rnd = 0; }
    else               { X = g_ecls; Wt = g_wc; bias = bc; Y = Yc; m0 = 0;               rnd = 0; }

    const uint32_t stile = smem_u32(smem) + OFF_TILE;

    const int lq = lane >> 3, lr = lane & 7;
    const int rowA = (wm * 64 + (lq & 1) * 8 + lr) * 36 + (lq >> 1) * 4;
    const int rowB = (wn * 64 + (lq >> 1) * 8 + lr) * 36 + (lq & 1) * 4;

    float c[4][8][4];
#pragma unroll
    for (int mt = 0; mt < 4; mt++)
#pragma unroll
        for (int nt = 0; nt < 8; nt++)
#pragma unroll
            for (int q = 0; q < 4; q++) c[mt][nt][q] = 0.0f;

    auto issue = [&](int kt, int s) {
        uint32_t ab = stile + s * STAGE_BYTES;
        uint32_t bb = ab + TILE_BYTES;
#pragma unroll
        for (int it = 0; it < 8; ++it) {
            int idx = tid + (it << 7);
            int r = idx >> 3, c4 = (idx & 7) << 2;
            uint32_t off = (uint32_t)(r * 36 + c4) * 4;
            cp16(ab + off, &X[(size_t)(m0 + r) * Dd + kt * 32 + c4]);
            cp16(bb + off, &Wt[(size_t)(n0 + r) * Dd + kt * 32 + c4]);
        }
    };

    issue(0, 0);
    CP_COMMIT();

    const int NKT = Dd / 32;  // 24
    for (int kt = 0; kt < NKT; ++kt) {
        CP_WAIT0();
        __syncthreads();
        if (kt + 1 < NKT) {
            issue(kt + 1, (kt + 1) & 1);
            CP_COMMIT();
        }

        const uint32_t ab = stile + (kt & 1) * STAGE_BYTES;
        const uint32_t bb = ab + TILE_BYTES;

#pragma unroll
        for (int ks = 0; ks < 4; ++ks) {
            int k0 = ks << 3;
            uint32_t a[4][4];
#pragma unroll
            for (int mt = 0; mt < 4; mt++)
                ldsm4(a[mt][0], a[mt][1], a[mt][2], a[mt][3],
                      ab + (uint32_t)(rowA + mt * 576 + k0) * 4);
#pragma unroll
            for (int p = 0; p < 4; p++) {
                uint32_t b0a, b1a, b0b, b1b;
                ldsm4(b0a, b1a, b0b, b1b,
                      bb + (uint32_t)(rowB + p * 576 + k0) * 4);
#pragma unroll
                for (int mt = 0; mt < 4; mt++)
                    mma_tf32(c[mt][2 * p], a[mt], b0a, b1a);
#pragma unroll
                for (int mt = 0; mt < 4; mt++)
                    mma_tf32(c[mt][2 * p + 1], a[mt], b0b, b1b);
            }
        }
    }

#pragma unroll
    for (int nt = 0; nt < 8; nt++) {
        int col = n0 + wn * 64 + nt * 8 + 2 * tg;
        float2 bvv = *(const float2*)&bias[col];
#pragma unroll
        for (int mt = 0; mt < 4; mt++) {
            int r = m0 + wm * 64 + mt * 16 + gid;
            float2 o0 = {c[mt][nt][0] + bvv.x, c[mt][nt][1] + bvv.y};
            float2 o1 = {c[mt][nt][2] + bvv.x, c[mt][nt][3] + bvv.y};
            if (rnd) {
                o0.x = __uint_as_float(f2tf(o0.x));
                o0.y = __uint_as_float(f2tf(o0.y));
                o1.x = __uint_as_float(f2tf(o1.x));
                o1.y = __uint_as_float(f2tf(o1.y));
            }
            *(float2*)&Y[(size_t)r * Hh + col] = o0;
            *(float2*)&Y[(size_t)(r + 8) * Hh + col] = o1;
        }
    }
}

// ---------------------------------------------------------------------------
// Attention core: one CTA per (e,b), 128 threads (4 warps, 64x64 tiles).
//   Fragment-register softmax + pbar (no P smem round trip).
// ---------------------------------------------------------------------------
#define ATTN_SMEM (OFF_TILE + 2 * STAGE_BYTES)

__global__ __launch_bounds__(128, 3)
void attn_mma(float* __restrict__ pbar_out)
{
    extern __shared__ char smem[];

    const int tid = threadIdx.x;
    const int wid = tid >> 5;
    const int lane = tid & 31;
    const int gid = lane >> 2;
    const int tg = lane & 3;
    const int wm = wid & 1;
    const int wn = wid >> 1;
    const int e = blockIdx.x >> 5;
    const int b = blockIdx.x & 31;

    const float* __restrict__ Q = g_q + (size_t)e * Ss * Hh;
    const float* __restrict__ K = g_k + (size_t)b * Ss * Hh;

    const uint32_t stile = smem_u32(smem) + OFF_TILE;

    const int lq = lane >> 3, lr = lane & 7;
    const int rowA = (wm * 64 + (lq & 1) * 8 + lr) * 36 + (lq >> 1) * 4;
    const int rowB = (wn * 64 + (lq >> 1) * 8 + lr) * 36 + (lq & 1) * 4;

    float c[4][8][4];
#pragma unroll
    for (int mt = 0; mt < 4; mt++)
#pragma unroll
        for (int nt = 0; nt < 8; nt++)
#pragma unroll
            for (int q = 0; q < 4; q++) c[mt][nt][q] = 0.0f;

    auto issue = [&](int kt, int s) {
        uint32_t qb = stile + s * STAGE_BYTES;
        uint32_t kb = qb + TILE_BYTES;
#pragma unroll
        for (int it = 0; it < 8; ++it) {
            int idx = tid + (it << 7);
            int r = idx >> 3, c4 = (idx & 7) << 2;
            uint32_t off = (uint32_t)(r * 36 + c4) * 4;
            cp16(qb + off, &Q[(size_t)r * Hh + kt * 32 + c4]);
            cp16(kb + off, &K[(size_t)r * Hh + kt * 32 + c4]);
        }
    };

    issue(0, 0);
    CP_COMMIT();

    const int NKT = Hh / 32;  // 24
    for (int kt = 0; kt < NKT; ++kt) {
        CP_WAIT0();
        __syncthreads();
        if (kt + 1 < NKT) {
            issue(kt + 1, (kt + 1) & 1);
            CP_COMMIT();
        }

        const uint32_t qb = stile + (kt & 1) * STAGE_BYTES;
        const uint32_t kb = qb + TILE_BYTES;

#pragma unroll
        for (int ks = 0; ks < 4; ++ks) {
            int k0 = ks << 3;
            uint32_t a[4][4];
#pragma unroll
            for (int mt = 0; mt < 4; mt++)
                ldsm4(a[mt][0], a[mt][1], a[mt][2], a[mt][3],
                      qb + (uint32_t)(rowA + mt * 576 + k0) * 4);
#pragma unroll
            for (int p = 0; p < 4; p++) {
                uint32_t b0a, b1a, b0b, b1b;
                ldsm4(b0a, b1a, b0b, b1b,
                      kb + (uint32_t)(rowB + p * 576 + k0) * 4);
#pragma unroll
                for (int mt = 0; mt < 4; mt++)
                    mma_tf32(c[mt][2 * p], a[mt], b0a, b1a);
#pragma unroll
                for (int mt = 0; mt < 4; mt++)
                    mma_tf32(c[mt][2 * p + 1], a[mt], b0b, b1b);
            }
        }
    }

    // --- register softmax + pbar ---
    float* rowmax = (float*)(smem + OFF_TILE);          // [2][128]
    float* rowsum = (float*)(smem + OFF_TILE + 1024);   // [2][128]
    float* colred = (float*)(smem + OFF_TILE + 2048);   // [2][128]

    const float scale = 0.0360843918243516f;  // 1/sqrt(768)

    float rm[8];
#pragma unroll
    for (int mt = 0; mt < 4; mt++)
#pragma unroll
        for (int hi = 0; hi < 2; hi++) {
            float m = -1e30f;
#pragma unroll
            for (int nt = 0; nt < 8; nt++) {
                m = fmaxf(m, c[mt][nt][hi * 2 + 0]);
                m = fmaxf(m, c[mt][nt][hi * 2 + 1]);
            }
            rm[mt * 2 + hi] = m;
        }
#pragma unroll
    for (int i = 0; i < 8; i++) {
        rm[i] = fmaxf(rm[i], __shfl_xor_sync(0xffffffffu, rm[i], 1));
        rm[i] = fmaxf(rm[i], __shfl_xor_sync(0xffffffffu, rm[i], 2));
    }
    if (tg == 0) {
#pragma unroll
        for (int i = 0; i < 8; i++) {
            int r = wm * 64 + (i >> 1) * 16 + (i & 1) * 8 + gid;
            rowmax[wn * 128 + r] = rm[i];
        }
    }
    __syncthreads();
#pragma unroll
    for (int i = 0; i < 8; i++) {
        int r = wm * 64 + (i >> 1) * 16 + (i & 1) * 8 + gid;
        rm[i] = fmaxf(rm[i], rowmax[(wn ^ 1) * 128 + r]);
    }

    float rs[8];
#pragma unroll
    for (int i = 0; i < 8; i++) rs[i] = 0.0f;
#pragma unroll
    for (int mt = 0; mt < 4; mt++)
#pragma unroll
        for (int nt = 0; nt < 8; nt++)
#pragma unroll
            for (int q = 0; q < 4; q++) {
                int i = mt * 2 + (q >> 1);
                float ev = __expf((c[mt][nt][q] - rm[i]) * scale);
                c[mt][nt][q] = ev;
                rs[i] += ev;
            }
#pragma unroll
    for (int i = 0; i < 8; i++) {
        rs[i] += __shfl_xor_sync(0xffffffffu, rs[i], 1);
        rs[i] += __shfl_xor_sync(0xffffffffu, rs[i], 2);
    }
    if (tg == 0) {
#pragma unroll
        for (int i = 0; i < 8; i++) {
            int r = wm * 64 + (i >> 1) * 16 + (i & 1) * 8 + gid;
            rowsum[wn * 128 + r] = rs[i];
        }
    }
    __syncthreads();
    float inv[8];
#pragma unroll
    for (int i = 0; i < 8; i++) {
        int r = wm * 64 + (i >> 1) * 16 + (i & 1) * 8 + gid;
        inv[i] = 1.0f / (rs[i] + rowsum[(wn ^ 1) * 128 + r]);
    }

    float pp[16];
#pragma unroll
    for (int j = 0; j < 16; j++) pp[j] = 0.0f;
#pragma unroll
    for (int mt = 0; mt < 4; mt++)
#pragma unroll
        for (int nt = 0; nt < 8; nt++)
#pragma unroll
            for (int q = 0; q < 4; q++) {
                int i = mt * 2 + (q >> 1);
                pp[nt * 2 + (q & 1)] += c[mt][nt][q] * inv[i];
            }
#pragma unroll
    for (int j = 0; j < 16; j++) {
        pp[j] += __shfl_xor_sync(0xffffffffu, pp[j], 4);
        pp[j] += __shfl_xor_sync(0xffffffffu, pp[j], 8);
        pp[j] += __shfl_xor_sync(0xffffffffu, pp[j], 16);
    }
    if (gid == 0) {
#pragma unroll
        for (int nt = 0; nt < 8; nt++)
#pragma unroll
            for (int par = 0; par < 2; par++) {
                int col = wn * 64 + nt * 8 + 2 * tg + par;
                colred[wm * 128 + col] = pp[nt * 2 + par];
            }
    }
    __syncthreads();
    if (tid < 128)
        pbar_out[(size_t)blockIdx.x * Ss + tid] = colred[tid] + colred[128 + tid];
}

// ---------------------------------------------------------------------------
// ctx + LN + dual score: grid (16 etiles, 32 b), 256 threads, 8 e per CTA.
// (round-14 proven version: scalar 3-way V loads, regs 63)
// ---------------------------------------------------------------------------
#define CTX_E 8
#define CTX_STRIDE 776
#define CTX_SMEM (CTX_E * 128 * 4 + CTX_E * CTX_STRIDE * 4)

__global__ __launch_bounds__(256)
void ctx_score(const float* __restrict__ ecls, const float* __restrict__ mcls,
               const float* __restrict__ lng, const float* __restrict__ lnb,
               float* __restrict__ out)
{
    extern __shared__ char smem[];
    float* pb = (float*)smem;                           // [8][128]
    float* ctx_s = (float*)(smem + CTX_E * 128 * 4);    // [8][776]

    const int tid = threadIdx.x;
    const int e0 = blockIdx.x * CTX_E;
    const int b = blockIdx.y;

    const float* __restrict__ V = g_v + (size_t)b * Ss * Hh;

#pragma unroll
    for (int it = 0; it < 4; ++it) {
        int i = tid + it * 256;
        int el = i >> 7, t = i & 127;
        pb[el * 128 + t] = g_pbar[(size_t)((e0 + el) * Bb + b) * Ss + t];
    }
    __syncthreads();

    float acc[CTX_E][3];
#pragma unroll
    for (int el = 0; el < CTX_E; el++)
#pragma unroll
        for (int j = 0; j < 3; j++) acc[el][j] = 0.0f;

#pragma unroll 4
    for (int t = 0; t < Ss; t++) {
        const float* vr = V + (size_t)t * Hh + tid;
        float v0 = vr[0], v1 = vr[256], v2 = vr[512];
#pragma unroll
        for (int el = 0; el < CTX_E; el++) {
            float p = pb[el * 128 + t];
            acc[el][0] += p * v0;
            acc[el][1] += p * v1;
            acc[el][2] += p * v2;
        }
    }
    const float invS = 1.0f / (float)Ss;
#pragma unroll
    for (int el = 0; el < CTX_E; el++) {
        ctx_s[el * CTX_STRIDE + tid]       = acc[el][0] * invS;
        ctx_s[el * CTX_STRIDE + tid + 256] = acc[el][1] * invS;
        ctx_s[el * CTX_STRIDE + tid + 512] = acc[el][2] * invS;
    }
    __syncthreads();

    const int g = tid >> 5;
    const int i = tid & 31;
    const int eg = e0 + g;
    const float* crow = &ctx_s[g * CTX_STRIDE];

    float lsum = 0.0f, lsq = 0.0f;
#pragma unroll
    for (int j = 0; j < 24; ++j) {
        float x = crow[i + 32 * j];
        lsum += x;
        lsq += x * x;
    }
#pragma unroll
    for (int o = 16; o > 0; o >>= 1) {
        lsum += __shfl_xor_sync(0xffffffffu, lsum, o);
        lsq  += __shfl_xor_sync(0xffffffffu, lsq, o);
    }
    const float mu = lsum * (1.0f / (float)Hh);
    const float var = lsq * (1.0f / (float)Hh) - mu * mu;
    const float rstd = rsqrtf(var + LN_EPS);

    const float* __restrict__ cfc = g_c + (size_t)eg * Hh;
    const float* __restrict__ er = ecls + (size_t)eg * Dd;
    const float* __restrict__ mr = mcls + (size_t)b * Dd;
    float p1 = 0.0f, p2 = 0.0f;
#pragma unroll
    for (int j = 0; j < 24; ++j) {
        int h = i + 32 * j;
        float x = (crow[h] - mu) * rstd * lng[h] + lnb[h];
        p1 += cfc[h] * x;
        p2 += mr[h] * er[h];
    }
#pragma unroll
    for (int o = 16; o > 0; o >>= 1) {
        p1 += __shfl_xor_sync(0xffffffffu, p1, o);
        p2 += __shfl_xor_sync(0xffffffffu, p2, o);
    }
    if (i == 0) out[(size_t)b * Ee + eg] = 0.5f * (p1 + p2);
}

// ---------------------------------------------------------------------------
extern "C" void kernel_launch(void* const* d_in, const int* in_sizes, int n_in,
                              void* d_out, int out_size)
{
    const float* ecls = (const float*)d_in[0];
    const float* etok = (const float*)d_in[1];
    const float* mcls = (const float*)d_in[2];
    const float* mtok = (const float*)d_in[3];
    const float* Wq = (const float*)d_in[4];
    const float* bq = (const float*)d_in[5];
    const float* Wk = (const float*)d_in[6];
    const float* bk = (const float*)d_in[7];
    const float* Wv = (const float*)d_in[8];
    const float* bv = (const float*)d_in[9];
    const float* Wc = (const float*)d_in[10];
    const float* bc = (const float*)d_in[11];
    const float* lng = (const float*)d_in[12];
    const float* lnb = (const float*)d_in[13];
    float* out = (float*)d_out;

    float *q_ptr, *k_ptr, *v_ptr, *c_ptr, *pbar_ptr;
    cudaGetSymbolAddress((void**)&q_ptr, g_q);
    cudaGetSymbolAddress((void**)&k_ptr, g_k);
    cudaGetSymbolAddress((void**)&v_ptr, g_v);
    cudaGetSymbolAddress((void**)&c_ptr, g_c);
    cudaGetSymbolAddress((void**)&pbar_ptr, g_pbar);

    cudaFuncSetAttribute(proj_mma, cudaFuncAttributeMaxDynamicSharedMemorySize, GEMM_SMEM);
    cudaFuncSetAttribute(attn_mma, cudaFuncAttributeMaxDynamicSharedMemorySize, ATTN_SMEM);
    cudaFuncSetAttribute(ctx_score, cudaFuncAttributeMaxDynamicSharedMemorySize, CTX_SMEM);

    prep<<<NB_PREP, 256>>>(etok, mtok, ecls, Wq, Wk, Wv, Wc);

    proj_mma<<<dim3(Hh / 128, 193), 128, GEMM_SMEM>>>(
        bq, bk, bv, bc, q_ptr, k_ptr, v_ptr, c_ptr);

    attn_mma<<<dim3(Ee * Bb), 128, ATTN_SMEM>>>(pbar_ptr);

    ctx_score<<<dim3(Ee / CTX_E, Bb), 256, CTX_SMEM>>>(ecls, mcls, lng, lnb, out);
}

// round 17
// speedup vs baseline: 1.7975x; 1.7313x over previous
#include <cuda_runtime.h>
#include <cuda_fp16.h>
#include <cstdint>
#include <math.h>

#define Dd 768
#define Hh 768
#define Ee 128
#define Bb 32
#define Ss 128
#define LN_EPS 1e-5f

// Scratch (static device arrays are allowed)
__device__ __half g_q[Ee * Ss * Hh];   // fp16 q
__device__ __half g_k[Bb * Ss * Hh];   // fp16 k
__device__ float  g_v[Bb * Ss * Hh];   // exact fp32
__device__ float  g_c[Ee * Hh];        // exact fp32
__device__ float  g_pbar[Ee * Bb * Ss];
// fp16 copies of inputs
__device__ __half g_etok[Ee * Ss * Dd];
__device__ __half g_mtok[Bb * Ss * Dd];
__device__ __half g_ecls[Ee * Dd];
// fp16 TRANSPOSED weights: [n][k]
__device__ __half g_wq[Hh * Dd];
__device__ __half g_wk[Hh * Dd];
__device__ __half g_wv[Hh * Dd];
__device__ __half g_wc[Hh * Dd];

// ---------------------------------------------------------------------------
// helpers
// ---------------------------------------------------------------------------
__device__ __forceinline__ uint32_t smem_u32(const void* p) {
    uint32_t a;
    asm("{ .reg .u64 t; cvta.to.shared.u64 t, %1; cvt.u32.u64 %0, t; }"
        : "=r"(a) : "l"(p));
    return a;
}

// L1-bypass async copy
__device__ __forceinline__ void cp16(uint32_t dst, const void* src) {
    asm volatile("cp.async.cg.shared.global [%0], [%1], 16;"
                 :: "r"(dst), "l"(src));
}
#define CP_COMMIT() asm volatile("cp.async.commit_group;" ::: "memory")
#define CP_WAIT0()  asm volatile("cp.async.wait_group 0;" ::: "memory")

__device__ __forceinline__ void mma_f16(float* c, const uint32_t* a,
                                        uint32_t b0, uint32_t b1) {
    asm volatile(
        "mma.sync.aligned.m16n8k16.row.col.f32.f16.f16.f32 "
        "{%0,%1,%2,%3}, {%4,%5,%6,%7}, {%8,%9}, {%0,%1,%2,%3};\n"
        : "+f"(c[0]), "+f"(c[1]), "+f"(c[2]), "+f"(c[3])
        : "r"(a[0]), "r"(a[1]), "r"(a[2]), "r"(a[3]), "r"(b0), "r"(b1));
}

__device__ __forceinline__ void ldsm4(uint32_t& r0, uint32_t& r1,
                                      uint32_t& r2, uint32_t& r3, uint32_t addr) {
    asm volatile("ldmatrix.sync.aligned.m8n8.x4.shared.b16 {%0,%1,%2,%3}, [%4];"
                 : "=r"(r0), "=r"(r1), "=r"(r2), "=r"(r3) : "r"(addr));
}

// ---------------------------------------------------------------------------
// Merged prep pass: activation fp16 conversion + weight transpose/convert.
// ---------------------------------------------------------------------------
#define N4_ETOK (Ee * Ss * Dd / 4)
#define N4_MTOK (Bb * Ss * Dd / 4)
#define N4_ECLS (Ee * Dd / 4)
#define N4_TOTAL (N4_ETOK + N4_MTOK + N4_ECLS)
#define NB_ROUND (N4_TOTAL / 256)
#define NB_WT    (24 * 24 * 4)
#define NB_PREP  (NB_ROUND + NB_WT)

__global__ __launch_bounds__(256)
void prep(const float* __restrict__ etok, const float* __restrict__ mtok,
          const float* __restrict__ ecls,
          const float* __restrict__ Wq, const float* __restrict__ Wk,
          const float* __restrict__ Wv, const float* __restrict__ Wc)
{
    __shared__ float t[32][33];
    const int bid = blockIdx.x;
    const int tid = threadIdx.x;

    if (bid < NB_ROUND) {
        int idx = bid * 256 + tid;
        const float4* src;
        __half* dst;
        int off = idx;
        if (off < N4_ETOK) { src = (const float4*)etok; dst = g_etok; }
        else if ((off -= N4_ETOK) < N4_MTOK) { src = (const float4*)mtok; dst = g_mtok; }
        else { off -= N4_MTOK; src = (const float4*)ecls; dst = g_ecls; }
        float4 v = src[off];
        __half2 h0 = __floats2half2_rn(v.x, v.y);
        __half2 h1 = __floats2half2_rn(v.z, v.w);
        uint2 o = {*(uint32_t*)&h0, *(uint32_t*)&h1};
        *(uint2*)&dst[(size_t)off * 4] = o;
        return;
    }

    // weight transpose + fp16 convert
    int w = bid - NB_ROUND;
    int z = w / 576;
    int rem = w - z * 576;
    int bx = rem % 24, by = rem / 24;
    const float* W;
    __half* Wt;
    switch (z) {
        case 0: W = Wq; Wt = g_wq; break;
        case 1: W = Wk; Wt = g_wk; break;
        case 2: W = Wv; Wt = g_wv; break;
        default: W = Wc; Wt = g_wc; break;
    }
    const int tx = tid & 31, ty = tid >> 5;
    const int x = bx * 32 + tx;
    const int y0 = by * 32;
#pragma unroll
    for (int j = 0; j < 32; j += 8)
        t[ty + j][tx] = W[(size_t)(y0 + ty + j) * Hh + x];
    __syncthreads();
    const int xn = bx * 32;
#pragma unroll
    for (int j = 0; j < 32; j += 8)
        Wt[(size_t)(xn + ty + j) * Dd + y0 + tx] = __float2half_rn(t[tx][ty + j]);
}

// ---------------------------------------------------------------------------
// fp16 GEMM tiles: 128 rows x 64 halves (128B data), stride 144B (pad).
// K-chunk 64 halves -> 4 k16 mma steps per chunk; 12 chunks for K=768.
// ---------------------------------------------------------------------------
#define ROW_STRIDE 144
#define TILE_BYTES (128 * ROW_STRIDE)      // 18432
#define STAGE_BYTES (2 * TILE_BYTES)       // 36864
#define OFF_TILE 1024
#define GEMM_SMEM (OFF_TILE + 2 * STAGE_BYTES)

// ---------------------------------------------------------------------------
// Merged projection: all 4 GEMMs, fp16 mma.
// grid (6, 193): by in [0,128) q | [128,160) k | [160,192) v | 192 cls
// ---------------------------------------------------------------------------
__global__ __launch_bounds__(128, 3)
void proj_mma(const float* __restrict__ bq, const float* __restrict__ bk,
              const float* __restrict__ bv, const float* __restrict__ bc,
              __half* __restrict__ Yq, __half* __restrict__ Yk,
              float* __restrict__ Yv, float* __restrict__ Yc)
{
    extern __shared__ char smem[];

    const int tid = threadIdx.x;
    const int wid = tid >> 5;
    const int lane = tid & 31;
    const int gid = lane >> 2;
    const int tg = lane & 3;
    const int wm = wid & 1;
    const int wn = wid >> 1;
    const int n0 = blockIdx.x << 7;

    const int by = blockIdx.y;
    const __half *X, *Wt;
    const float* bias;
    __half* Yh = nullptr;
    float* Yf = nullptr;
    int m0, rnd;
    if (by < 128)      { X = g_etok; Wt = g_wq; bias = bq; Yh = Yq; m0 = by << 7;         rnd = 1; }
    else if (by < 160) { X = g_mtok; Wt = g_wk; bias = bk; Yh = Yk; m0 = (by - 128) << 7; rnd = 1; }
    else if (by < 192) { X = g_mtok; Wt = g_wv; bias = bv; Yf = Yv; m0 = (by - 160) << 7; rnd = 0; }
    else               { X = g_ecls; Wt = g_wc; bias = bc; Yf = Yc; m0 = 0;               rnd = 0; }

    const uint32_t stile = smem_u32(smem) + OFF_TILE;

    const int lq = lane >> 3, lr = lane & 7;
    const int rowA = (wm * 64 + (lq & 1) * 8 + lr) * ROW_STRIDE + (lq >> 1) * 16;
    const int rowB = (wn * 64 + (lq >> 1) * 8 + lr) * ROW_STRIDE + (lq & 1) * 16;

    float c[4][8][4];
#pragma unroll
    for (int mt = 0; mt < 4; mt++)
#pragma unroll
        for (int nt = 0; nt < 8; nt++)
#pragma unroll
            for (int q = 0; q < 4; q++) c[mt][nt][q] = 0.0f;

    auto issue = [&](int kt, int s) {
        uint32_t ab = stile + s * STAGE_BYTES;
        uint32_t bb = ab + TILE_BYTES;
#pragma unroll
        for (int it = 0; it < 8; ++it) {
            int idx = tid + (it << 7);
            int r = idx >> 3, c8 = idx & 7;
            uint32_t off = (uint32_t)(r * ROW_STRIDE + c8 * 16);
            cp16(ab + off, &X[(size_t)(m0 + r) * Dd + kt * 64 + c8 * 8]);
            cp16(bb + off, &Wt[(size_t)(n0 + r) * Dd + kt * 64 + c8 * 8]);
        }
    };

    issue(0, 0);
    CP_COMMIT();

    const int NKT = Dd / 64;  // 12
    for (int kt = 0; kt < NKT; ++kt) {
        CP_WAIT0();
        __syncthreads();
        if (kt + 1 < NKT) {
            issue(kt + 1, (kt + 1) & 1);
            CP_COMMIT();
        }

        const uint32_t ab = stile + (kt & 1) * STAGE_BYTES;
        const uint32_t bb = ab + TILE_BYTES;

#pragma unroll
        for (int ks = 0; ks < 4; ++ks) {
            int kso = ks * 32;
            uint32_t a[4][4];
#pragma unroll
            for (int mt = 0; mt < 4; mt++)
                ldsm4(a[mt][0], a[mt][1], a[mt][2], a[mt][3],
                      ab + (uint32_t)(rowA + mt * 16 * ROW_STRIDE + kso));
#pragma unroll
            for (int p = 0; p < 4; p++) {
                uint32_t b0a, b1a, b0b, b1b;
                ldsm4(b0a, b1a, b0b, b1b,
                      bb + (uint32_t)(rowB + p * 16 * ROW_STRIDE + kso));
#pragma unroll
                for (int mt = 0; mt < 4; mt++)
                    mma_f16(c[mt][2 * p], a[mt], b0a, b1a);
#pragma unroll
                for (int mt = 0; mt < 4; mt++)
                    mma_f16(c[mt][2 * p + 1], a[mt], b0b, b1b);
            }
        }
    }

#pragma unroll
    for (int nt = 0; nt < 8; nt++) {
        int col = n0 + wn * 64 + nt * 8 + 2 * tg;
        float2 bvv = *(const float2*)&bias[col];
#pragma unroll
        for (int mt = 0; mt < 4; mt++) {
            int r = m0 + wm * 64 + mt * 16 + gid;
            float2 o0 = {c[mt][nt][0] + bvv.x, c[mt][nt][1] + bvv.y};
            float2 o1 = {c[mt][nt][2] + bvv.x, c[mt][nt][3] + bvv.y};
            if (rnd) {
                __half2 h0 = __floats2half2_rn(o0.x, o0.y);
                __half2 h1 = __floats2half2_rn(o1.x, o1.y);
                *(__half2*)&Yh[(size_t)r * Hh + col] = h0;
                *(__half2*)&Yh[(size_t)(r + 8) * Hh + col] = h1;
            } else {
                *(float2*)&Yf[(size_t)r * Hh + col] = o0;
                *(float2*)&Yf[(size_t)(r + 8) * Hh + col] = o1;
            }
        }
    }
}

// ---------------------------------------------------------------------------
// Attention core: one CTA per (e,b), 128 threads, fp16 mma, 64x64 warp tiles.
//   Register softmax + pbar epilogue (proven round-14 structure).
// ---------------------------------------------------------------------------
#define ATTN_SMEM (OFF_TILE + 2 * STAGE_BYTES)

__global__ __launch_bounds__(128, 3)
void attn_mma(float* __restrict__ pbar_out)
{
    extern __shared__ char smem[];

    const int tid = threadIdx.x;
    const int wid = tid >> 5;
    const int lane = tid & 31;
    const int gid = lane >> 2;
    const int tg = lane & 3;
    const int wm = wid & 1;
    const int wn = wid >> 1;
    const int e = blockIdx.x >> 5;
    const int b = blockIdx.x & 31;

    const __half* __restrict__ Q = g_q + (size_t)e * Ss * Hh;
    const __half* __restrict__ K = g_k + (size_t)b * Ss * Hh;

    const uint32_t stile = smem_u32(smem) + OFF_TILE;

    const int lq = lane >> 3, lr = lane & 7;
    const int rowA = (wm * 64 + (lq & 1) * 8 + lr) * ROW_STRIDE + (lq >> 1) * 16;
    const int rowB = (wn * 64 + (lq >> 1) * 8 + lr) * ROW_STRIDE + (lq & 1) * 16;

    float c[4][8][4];
#pragma unroll
    for (int mt = 0; mt < 4; mt++)
#pragma unroll
        for (int nt = 0; nt < 8; nt++)
#pragma unroll
            for (int q = 0; q < 4; q++) c[mt][nt][q] = 0.0f;

    auto issue = [&](int kt, int s) {
        uint32_t qb = stile + s * STAGE_BYTES;
        uint32_t kb = qb + TILE_BYTES;
#pragma unroll
        for (int it = 0; it < 8; ++it) {
            int idx = tid + (it << 7);
            int r = idx >> 3, c8 = idx & 7;
            uint32_t off = (uint32_t)(r * ROW_STRIDE + c8 * 16);
            cp16(qb + off, &Q[(size_t)r * Hh + kt * 64 + c8 * 8]);
            cp16(kb + off, &K[(size_t)r * Hh + kt * 64 + c8 * 8]);
        }
    };

    issue(0, 0);
    CP_COMMIT();

    const int NKT = Hh / 64;  // 12
    for (int kt = 0; kt < NKT; ++kt) {
        CP_WAIT0();
        __syncthreads();
        if (kt + 1 < NKT) {
            issue(kt + 1, (kt + 1) & 1);
            CP_COMMIT();
        }

        const uint32_t qb = stile + (kt & 1) * STAGE_BYTES;
        const uint32_t kb = qb + TILE_BYTES;

#pragma unroll
        for (int ks = 0; ks < 4; ++ks) {
            int kso = ks * 32;
            uint32_t a[4][4];
#pragma unroll
            for (int mt = 0; mt < 4; mt++)
                ldsm4(a[mt][0], a[mt][1], a[mt][2], a[mt][3],
                      qb + (uint32_t)(rowA + mt * 16 * ROW_STRIDE + kso));
#pragma unroll
            for (int p = 0; p < 4; p++) {
                uint32_t b0a, b1a, b0b, b1b;
                ldsm4(b0a, b1a, b0b, b1b,
                      kb + (uint32_t)(rowB + p * 16 * ROW_STRIDE + kso));
#pragma unroll
                for (int mt = 0; mt < 4; mt++)
                    mma_f16(c[mt][2 * p], a[mt], b0a, b1a);
#pragma unroll
                for (int mt = 0; mt < 4; mt++)
                    mma_f16(c[mt][2 * p + 1], a[mt], b0b, b1b);
            }
        }
    }

    // --- register softmax + pbar (buffers overlay stage 0; last chunk = stage 1)
    float* rowmax = (float*)(smem + OFF_TILE);          // [2][128]
    float* rowsum = (float*)(smem + OFF_TILE + 1024);   // [2][128]
    float* colred = (float*)(smem + OFF_TILE + 2048);   // [2][128]

    const float scale = 0.0360843918243516f;  // 1/sqrt(768)

    float rm[8];
#pragma unroll
    for (int mt = 0; mt < 4; mt++)
#pragma unroll
        for (int hi = 0; hi < 2; hi++) {
            float m = -1e30f;
#pragma unroll
            for (int nt = 0; nt < 8; nt++) {
                m = fmaxf(m, c[mt][nt][hi * 2 + 0]);
                m = fmaxf(m, c[mt][nt][hi * 2 + 1]);
            }
            rm[mt * 2 + hi] = m;
        }
#pragma unroll
    for (int i = 0; i < 8; i++) {
        rm[i] = fmaxf(rm[i], __shfl_xor_sync(0xffffffffu, rm[i], 1));
        rm[i] = fmaxf(rm[i], __shfl_xor_sync(0xffffffffu, rm[i], 2));
    }
    if (tg == 0) {
#pragma unroll
        for (int i = 0; i < 8; i++) {
            int r = wm * 64 + (i >> 1) * 16 + (i & 1) * 8 + gid;
            rowmax[wn * 128 + r] = rm[i];
        }
    }
    __syncthreads();
#pragma unroll
    for (int i = 0; i < 8; i++) {
        int r = wm * 64 + (i >> 1) * 16 + (i & 1) * 8 + gid;
        rm[i] = fmaxf(rm[i], rowmax[(wn ^ 1) * 128 + r]);
    }

    float rs[8];
#pragma unroll
    for (int i = 0; i < 8; i++) rs[i] = 0.0f;
#pragma unroll
    for (int mt = 0; mt < 4; mt++)
#pragma unroll
        for (int nt = 0; nt < 8; nt++)
#pragma unroll
            for (int q = 0; q < 4; q++) {
                int i = mt * 2 + (q >> 1);
                float ev = __expf((c[mt][nt][q] - rm[i]) * scale);
                c[mt][nt][q] = ev;
                rs[i] += ev;
            }
#pragma unroll
    for (int i = 0; i < 8; i++) {
        rs[i] += __shfl_xor_sync(0xffffffffu, rs[i], 1);
        rs[i] += __shfl_xor_sync(0xffffffffu, rs[i], 2);
    }
    if (tg == 0) {
#pragma unroll
        for (int i = 0; i < 8; i++) {
            int r = wm * 64 + (i >> 1) * 16 + (i & 1) * 8 + gid;
            rowsum[wn * 128 + r] = rs[i];
        }
    }
    __syncthreads();
    float inv[8];
#pragma unroll
    for (int i = 0; i < 8; i++) {
        int r = wm * 64 + (i >> 1) * 16 + (i & 1) * 8 + gid;
        inv[i] = 1.0f / (rs[i] + rowsum[(wn ^ 1) * 128 + r]);
    }

    float pp[16];
#pragma unroll
    for (int j = 0; j < 16; j++) pp[j] = 0.0f;
#pragma unroll
    for (int mt = 0; mt < 4; mt++)
#pragma unroll
        for (int nt = 0; nt < 8; nt++)
#pragma unroll
            for (int q = 0; q < 4; q++) {
                int i = mt * 2 + (q >> 1);
                pp[nt * 2 + (q & 1)] += c[mt][nt][q] * inv[i];
            }
#pragma unroll
    for (int j = 0; j < 16; j++) {
        pp[j] += __shfl_xor_sync(0xffffffffu, pp[j], 4);
        pp[j] += __shfl_xor_sync(0xffffffffu, pp[j], 8);
        pp[j] += __shfl_xor_sync(0xffffffffu, pp[j], 16);
    }
    if (gid == 0) {
#pragma unroll
        for (int nt = 0; nt < 8; nt++)
#pragma unroll
            for (int par = 0; par < 2; par++) {
                int col = wn * 64 + nt * 8 + 2 * tg + par;
                colred[wm * 128 + col] = pp[nt * 2 + par];
            }
    }
    __syncthreads();
    if (tid < 128)
        pbar_out[(size_t)blockIdx.x * Ss + tid] = colred[tid] + colred[128 + tid];
}

// ---------------------------------------------------------------------------
// ctx + LN + dual score: grid (16 etiles, 32 b), 256 threads, 8 e per CTA.
// (round-14/16 proven version)
// ---------------------------------------------------------------------------
#define CTX_E 8
#define CTX_STRIDE 776
#define CTX_SMEM (CTX_E * 128 * 4 + CTX_E * CTX_STRIDE * 4)

__global__ __launch_bounds__(256)
void ctx_score(const float* __restrict__ ecls, const float* __restrict__ mcls,
               const float* __restrict__ lng, const float* __restrict__ lnb,
               float* __restrict__ out)
{
    extern __shared__ char smem[];
    float* pb = (float*)smem;                           // [8][128]
    float* ctx_s = (float*)(smem + CTX_E * 128 * 4);    // [8][776]

    const int tid = threadIdx.x;
    const int e0 = blockIdx.x * CTX_E;
    const int b = blockIdx.y;

    const float* __restrict__ V = g_v + (size_t)b * Ss * Hh;

#pragma unroll
    for (int it = 0; it < 4; ++it) {
        int i = tid + it * 256;
        int el = i >> 7, t = i & 127;
        pb[el * 128 + t] = g_pbar[(size_t)((e0 + el) * Bb + b) * Ss + t];
    }
    __syncthreads();

    float acc[CTX_E][3];
#pragma unroll
    for (int el = 0; el < CTX_E; el++)
#pragma unroll
        for (int j = 0; j < 3; j++) acc[el][j] = 0.0f;

#pragma unroll 4
    for (int t = 0; t < Ss; t++) {
        const float* vr = V + (size_t)t * Hh + tid;
        float v0 = vr[0], v1 = vr[256], v2 = vr[512];
#pragma unroll
        for (int el = 0; el < CTX_E; el++) {
            float p = pb[el * 128 + t];
            acc[el][0] += p * v0;
            acc[el][1] += p * v1;
            acc[el][2] += p * v2;
        }
    }
    const float invS = 1.0f / (float)Ss;
#pragma unroll
    for (int el = 0; el < CTX_E; el++) {
        ctx_s[el * CTX_STRIDE + tid]       = acc[el][0] * invS;
        ctx_s[el * CTX_STRIDE + tid + 256] = acc[el][1] * invS;
        ctx_s[el * CTX_STRIDE + tid + 512] = acc[el][2] * invS;
    }
    __syncthreads();

    const int g = tid >> 5;
    const int i = tid & 31;
    const int eg = e0 + g;
    const float* crow = &ctx_s[g * CTX_STRIDE];

    float lsum = 0.0f, lsq = 0.0f;
#pragma unroll
    for (int j = 0; j < 24; ++j) {
        float x = crow[i + 32 * j];
        lsum += x;
        lsq += x * x;
    }
#pragma unroll
    for (int o = 16; o > 0; o >>= 1) {
        lsum += __shfl_xor_sync(0xffffffffu, lsum, o);
        lsq  += __shfl_xor_sync(0xffffffffu, lsq, o);
    }
    const float mu = lsum * (1.0f / (float)Hh);
    const float var = lsq * (1.0f / (float)Hh) - mu * mu;
    const float rstd = rsqrtf(var + LN_EPS);

    const float* __restrict__ cfc = g_c + (size_t)eg * Hh;
    const float* __restrict__ er = ecls + (size_t)eg * Dd;
    const float* __restrict__ mr = mcls + (size_t)b * Dd;
    float p1 = 0.0f, p2 = 0.0f;
#pragma unroll
    for (int j = 0; j < 24; ++j) {
        int h = i + 32 * j;
        float x = (crow[h] - mu) * rstd * lng[h] + lnb[h];
        p1 += cfc[h] * x;
        p2 += mr[h] * er[h];
    }
#pragma unroll
    for (int o = 16; o > 0; o >>= 1) {
        p1 += __shfl_xor_sync(0xffffffffu, p1, o);
        p2 += __shfl_xor_sync(0xffffffffu, p2, o);
    }
    if (i == 0) out[(size_t)b * Ee + eg] = 0.5f * (p1 + p2);
}

// ---------------------------------------------------------------------------
extern "C" void kernel_launch(void* const* d_in, const int* in_sizes, int n_in,
                              void* d_out, int out_size)
{
    const float* ecls = (const float*)d_in[0];
    const float* etok = (const float*)d_in[1];
    const float* mcls = (const float*)d_in[2];
    const float* mtok = (const float*)d_in[3];
    const float* Wq = (const float*)d_in[4];
    const float* bq = (const float*)d_in[5];
    const float* Wk = (const float*)d_in[6];
    const float* bk = (const float*)d_in[7];
    const float* Wv = (const float*)d_in[8];
    const float* bv = (const float*)d_in[9];
    const float* Wc = (const float*)d_in[10];
    const float* bc = (const float*)d_in[11];
    const float* lng = (const float*)d_in[12];
    const float* lnb = (const float*)d_in[13];
    float* out = (float*)d_out;

    __half *q_ptr, *k_ptr;
    float *v_ptr, *c_ptr, *pbar_ptr;
    cudaGetSymbolAddress((void**)&q_ptr, g_q);
    cudaGetSymbolAddress((void**)&k_ptr, g_k);
    cudaGetSymbolAddress((void**)&v_ptr, g_v);
    cudaGetSymbolAddress((void**)&c_ptr, g_c);
    cudaGetSymbolAddress((void**)&pbar_ptr, g_pbar);

    cudaFuncSetAttribute(proj_mma, cudaFuncAttributeMaxDynamicSharedMemorySize, GEMM_SMEM);
    cudaFuncSetAttribute(attn_mma, cudaFuncAttributeMaxDynamicSharedMemorySize, ATTN_SMEM);
    cudaFuncSetAttribute(ctx_score, cudaFuncAttributeMaxDynamicSharedMemorySize, CTX_SMEM);

    prep<<<NB_PREP, 256>>>(etok, mtok, ecls, Wq, Wk, Wv, Wc);

    proj_mma<<<dim3(Hh / 128, 193), 128, GEMM_SMEM>>>(
        bq, bk, bv, bc, q_ptr, k_ptr, v_ptr, c_ptr);

    attn_mma<<<dim3(Ee * Bb), 128, ATTN_SMEM>>>(pbar_ptr);

    ctx_score<<<dim3(Ee / CTX_E, Bb), 256, CTX_SMEM>>>(ecls, mcls, lng, lnb, out);
}